// round 7
// baseline (speedup 1.0000x reference)
#include <cuda_runtime.h>
#include <math.h>

// theta [B=4] degrees, image [C=3, H=80, W=80] -> out [B, C, H, W].
// Reference's dense [B,N,N] tent-weight matmul == bilinear gather with zero
// weight for out-of-grid taps (tent support <= 2 integer taps per axis).
//
// Floor-tuned config: grid(4,10) x block(80,8) == 25600 threads, 40 CTAs.
// dur_us tracks CTA/dispatch count on this overhead-bound kernel
// (600 CTAs -> 6.88us, 100 -> 6.53, 80 -> 6.21), so halve CTAs again.
// No integer div/mod on the thread path; all 12 image loads batched
// (one exposed L2 round, MLP=12).

#define B_ 4
#define C_ 3
#define H_ 80
#define W_ 80
#define HW_ (H_ * W_)

__global__ __launch_bounds__(640) void rot_bilinear_kernel(
    const float* __restrict__ theta,   // [B]
    const float* __restrict__ image,   // [C, H, W]
    float* __restrict__ out)           // [B, C, H, W]
{
    const int b = blockIdx.x;                          // uniform per CTA
    const int y = blockIdx.y * 8 + threadIdx.y;        // [0,80)
    const int x = threadIdx.x;                         // [0,80)

    const float cx = (W_ - 1) * 0.5f;
    const float cy = (H_ - 1) * 0.5f;

    const float th = __ldg(theta + b) * 0.017453292519943295f;  // deg2rad
    float sn, cs;
    __sincosf(th, &sn, &cs);

    const float x_rel = (float)x - cx;
    const float y_rel = (float)y - cy;

    const float sx = fmaf(cs, x_rel, fmaf(sn, y_rel, cx));    //  cos*x + sin*y + cx
    const float sy = fmaf(-sn, x_rel, fmaf(cs, y_rel, cy));   // -sin*x + cos*y + cy

    const int ix0 = __float2int_rd(sx);
    const int iy0 = __float2int_rd(sy);
    const float ax = sx - __int2float_rn(ix0);   // weight of ix0+1
    const float ay = sy - __int2float_rn(iy0);   // weight of iy0+1

    float wx0 = 1.0f - ax, wx1 = ax;
    float wy0 = 1.0f - ay, wy1 = ay;
    // zero weights for out-of-grid taps (matches reference truncated tent sum)
    if (ix0 < 0 || ix0 >= W_)         wx0 = 0.0f;
    if (ix0 + 1 < 0 || ix0 + 1 >= W_) wx1 = 0.0f;
    if (iy0 < 0 || iy0 >= H_)         wy0 = 0.0f;
    if (iy0 + 1 < 0 || iy0 + 1 >= H_) wy1 = 0.0f;

    // clamp indices so loads stay in-bounds (weight already zeroed)
    const int jx0 = min(max(ix0, 0), W_ - 1);
    const int jx1 = min(max(ix0 + 1, 0), W_ - 1);
    const int r0  = min(max(iy0, 0), H_ - 1) * W_;
    const int r1  = min(max(iy0 + 1, 0), H_ - 1) * W_;

    const float w00 = wy0 * wx0;
    const float w01 = wy0 * wx1;
    const float w10 = wy1 * wx0;
    const float w11 = wy1 * wx1;

    const int o00 = r0 + jx0, o01 = r0 + jx1;
    const int o10 = r1 + jx0, o11 = r1 + jx1;

    // Batch ALL 12 loads (3 channels x 4 taps): one exposed L2 round, MLP=12.
    float v00[C_], v01[C_], v10[C_], v11[C_];
    #pragma unroll
    for (int ch = 0; ch < C_; ch++) {
        const float* img = image + ch * HW_;
        v00[ch] = __ldg(img + o00);
        v01[ch] = __ldg(img + o01);
        v10[ch] = __ldg(img + o10);
        v11[ch] = __ldg(img + o11);
    }

    float* outp = out + b * (C_ * HW_) + y * W_ + x;
    #pragma unroll
    for (int ch = 0; ch < C_; ch++) {
        float v = w00 * v00[ch];
        v = fmaf(w01, v01[ch], v);
        v = fmaf(w10, v10[ch], v);
        v = fmaf(w11, v11[ch], v);
        outp[ch * HW_] = v;
    }
}

extern "C" void kernel_launch(void* const* d_in, const int* in_sizes, int n_in,
                              void* d_out, int out_size) {
    const float* theta = (const float*)d_in[0];   // [4]
    const float* image = (const float*)d_in[1];   // [3, 80, 80]
    float* out = (float*)d_out;                   // [4, 3, 80, 80]

    dim3 grid(4, 10);      // b, y-groups of 8
    dim3 block(80, 8);     // x, y-within-group  -> 640 threads
    rot_bilinear_kernel<<<grid, block>>>(theta, image, out);  // 25600 threads, 40 CTAs
}

// round 8
// speedup vs baseline: 1.1311x; 1.1311x over previous
#include <cuda_runtime.h>
#include <math.h>

// theta [B=4] degrees, image [C=3, H=80, W=80] -> out [B, C, H, W].
// Reference's dense [B,N,N] tent-weight matmul == bilinear gather with zero
// weight for out-of-grid taps (tent support <= 2 integer taps per axis).
//
// Final config (best measured mean): grid(4,20) x block(80,4), 80 CTAs,
// 25600 threads, one thread per (b,y,x) site covering all 3 channels.
// Zero integer div/mod on the thread path (b/y/x from launch geometry),
// all 12 image loads batched before the FMA tree (one exposed L2 round,
// MLP=12), fully coalesced stores. Kernel is launch-overhead-bound; body
// is ~<1us of the ~6.4us end-to-end measurement.

#define B_ 4
#define C_ 3
#define H_ 80
#define W_ 80
#define HW_ (H_ * W_)

__global__ __launch_bounds__(320) void rot_bilinear_kernel(
    const float* __restrict__ theta,   // [B]
    const float* __restrict__ image,   // [C, H, W]
    float* __restrict__ out)           // [B, C, H, W]
{
    const int b = blockIdx.x;                          // uniform per CTA
    const int y = blockIdx.y * 4 + threadIdx.y;        // [0,80)
    const int x = threadIdx.x;                         // [0,80)

    const float cx = (W_ - 1) * 0.5f;
    const float cy = (H_ - 1) * 0.5f;

    const float th = __ldg(theta + b) * 0.017453292519943295f;  // deg2rad
    float sn, cs;
    __sincosf(th, &sn, &cs);

    const float x_rel = (float)x - cx;
    const float y_rel = (float)y - cy;

    const float sx = fmaf(cs, x_rel, fmaf(sn, y_rel, cx));    //  cos*x + sin*y + cx
    const float sy = fmaf(-sn, x_rel, fmaf(cs, y_rel, cy));   // -sin*x + cos*y + cy

    const int ix0 = __float2int_rd(sx);
    const int iy0 = __float2int_rd(sy);
    const float ax = sx - __int2float_rn(ix0);   // weight of ix0+1
    const float ay = sy - __int2float_rn(iy0);   // weight of iy0+1

    float wx0 = 1.0f - ax, wx1 = ax;
    float wy0 = 1.0f - ay, wy1 = ay;
    // zero weights for out-of-grid taps (matches reference truncated tent sum)
    if (ix0 < 0 || ix0 >= W_)  wx0 = 0.0f;
    if (ix0 >= W_ - 1)         wx1 = 0.0f;   // ix0+1 out of range high
    if (ix0 < -1)              wx1 = 0.0f;   // ix0+1 out of range low
    if (iy0 < 0 || iy0 >= H_)  wy0 = 0.0f;
    if (iy0 >= H_ - 1)         wy1 = 0.0f;
    if (iy0 < -1)              wy1 = 0.0f;

    // clamp indices so loads stay in-bounds (weight already zeroed)
    const int jx0 = min(max(ix0, 0), W_ - 1);
    const int jx1 = min(max(ix0 + 1, 0), W_ - 1);
    const int r0  = min(max(iy0, 0), H_ - 1) * W_;
    const int r1  = min(max(iy0 + 1, 0), H_ - 1) * W_;

    const float w00 = wy0 * wx0;
    const float w01 = wy0 * wx1;
    const float w10 = wy1 * wx0;
    const float w11 = wy1 * wx1;

    const int o00 = r0 + jx0, o01 = r0 + jx1;
    const int o10 = r1 + jx0, o11 = r1 + jx1;

    // Batch ALL 12 loads (3 channels x 4 taps): one exposed L2 round, MLP=12.
    float v00[C_], v01[C_], v10[C_], v11[C_];
    #pragma unroll
    for (int ch = 0; ch < C_; ch++) {
        const float* img = image + ch * HW_;
        v00[ch] = __ldg(img + o00);
        v01[ch] = __ldg(img + o01);
        v10[ch] = __ldg(img + o10);
        v11[ch] = __ldg(img + o11);
    }

    float* outp = out + b * (C_ * HW_) + y * W_ + x;
    #pragma unroll
    for (int ch = 0; ch < C_; ch++) {
        float v = w00 * v00[ch];
        v = fmaf(w01, v01[ch], v);
        v = fmaf(w10, v10[ch], v);
        v = fmaf(w11, v11[ch], v);
        outp[ch * HW_] = v;
    }
}

extern "C" void kernel_launch(void* const* d_in, const int* in_sizes, int n_in,
                              void* d_out, int out_size) {
    const float* theta = (const float*)d_in[0];   // [4]
    const float* image = (const float*)d_in[1];   // [3, 80, 80]
    float* out = (float*)d_out;                   // [4, 3, 80, 80]

    dim3 grid(4, 20);      // b, y-groups of 4
    dim3 block(80, 4);     // x, y-within-group  -> 320 threads, 80 CTAs
    rot_bilinear_kernel<<<grid, block>>>(theta, image, out);  // 25600 threads
}